// round 14
// baseline (speedup 1.0000x reference)
#include <cuda_runtime.h>
#include <cstdint>

#define SS 512
#define BB 64
#define HH 1024
#define EE 512
#define VV 32000
#define TWOH 2048
#define KTOT 3584
#define G4 4096
#define NCHUNK 32           // 32 chunks of 16 rows (4 stages of 4)
#define NSPLIT 14
#define KSPLIT 256

// gates GEMM: MT=128, KC=32 (R10-proven)
#define GMT 128
#define KC 32
#define G_AHI 0
#define G_ALO 10240
#define G_BHI 20480
#define G_BLO 25600
#define G_STAGE 30720
// fc GEMM: MT=64, KC=64
#define FMT 64
#define FKC 64
#define F_AHI 0
#define F_ALO 9216          // 64*144
#define F_BHI 18432
#define F_BLO 27648
#define F_STAGE 36864

// ---------------- scratch ----------------------------------------------------
__device__ float g_hw[BB];
__device__ float g_eM[BB * NCHUNK];
__device__ float g_eL[BB * NCHUNK];
__device__ float g_ctx[(size_t)BB * NCHUNK * TWOH];
__device__ unsigned short g_Bhi[BB * KTOT];
__device__ unsigned short g_Blo[BB * KTOT];
__device__ unsigned short g_h1hi[BB * HH];
__device__ unsigned short g_h1lo[BB * HH];
__device__ float g_gatesP[NSPLIT * G4 * BB];  // [s][m][b]

__device__ __forceinline__ float sigm(float x) { return 1.f / (1.f + __expf(-x)); }

__device__ __forceinline__ void cpa16(uint32_t s, const void* g) {
    asm volatile("cp.async.cg.shared.global [%0], [%1], 16;" :: "r"(s), "l"(g));
}
__device__ __forceinline__ void cpa_commit() { asm volatile("cp.async.commit_group;"); }
__device__ __forceinline__ void cpa_wait0()  { asm volatile("cp.async.wait_group 0;"); }
__device__ __forceinline__ void cpa_wait1()  { asm volatile("cp.async.wait_group 1;"); }

__device__ __forceinline__ void ldsm4(uint32_t* r, uint32_t addr) {
    asm volatile("ldmatrix.sync.aligned.m8n8.x4.shared.b16 {%0,%1,%2,%3}, [%4];"
        : "=r"(r[0]), "=r"(r[1]), "=r"(r[2]), "=r"(r[3]) : "r"(addr));
}
__device__ __forceinline__ void mma16816(float* d, const uint32_t* a, const uint32_t* b) {
    asm volatile("mma.sync.aligned.m16n8k16.row.col.f32.bf16.bf16.f32 "
        "{%0,%1,%2,%3},{%4,%5,%6,%7},{%8,%9},{%0,%1,%2,%3};"
        : "+f"(d[0]), "+f"(d[1]), "+f"(d[2]), "+f"(d[3])
        : "r"(a[0]), "r"(a[1]), "r"(a[2]), "r"(a[3]), "r"(b[0]), "r"(b[1]));
}
__device__ __forceinline__ void st4(uint32_t a, uint32_t x, uint32_t y, uint32_t z, uint32_t w) {
    asm volatile("st.shared.v4.u32 [%0], {%1,%2,%3,%4};" :: "r"(a), "r"(x), "r"(y), "r"(z), "r"(w));
}

__device__ __forceinline__ void split16(float x, unsigned short& hi, unsigned short& lo) {
    uint32_t bx = __float_as_uint(x);
    hi = (unsigned short)(bx >> 16);
    float lf = x - __uint_as_float(bx & 0xFFFF0000u);
    lo = (unsigned short)(__float_as_uint(lf) >> 16);
}

// ---------------- K0 ----------------------------------------------------------
__global__ void k_hw(const float* __restrict__ hidden, const float* __restrict__ Wen) {
    int b = blockIdx.x, tid = threadIdx.x;
    float p = 0.f;
    for (int k = tid; k < HH; k += 128) p += hidden[b * HH + k] * Wen[k];
    __shared__ float red[128];
    red[tid] = p; __syncthreads();
    for (int o = 64; o >= 32; o >>= 1) { if (tid < o) red[tid] += red[tid + o]; __syncthreads(); }
    if (tid < 32) {
        float v = red[tid];
        for (int o = 16; o; o >>= 1) v += __shfl_xor_sync(~0u, v, o);
        if (tid == 0) g_hw[b] = v;
    }
}

// ---------------- K1: attention (4 stages of 4 rows, pipelined cp.async) ------
__global__ __launch_bounds__(256)
void k_attn(const float* __restrict__ enc, const float* __restrict__ Wen,
            const float* __restrict__ be) {
    extern __shared__ float sm[];
    float* rowbuf[2] = { sm, sm + 4 * TWOH };       // 2 x [4][2048]
    float* we = sm + 8 * TWOH;                      // [2048]
    __shared__ float sEp[8];
    const int chunk = blockIdx.x, b = blockIdx.y, tid = threadIdx.x;
    const int w = tid >> 5, lane = tid & 31;
    uint32_t srb[2] = { (uint32_t)__cvta_generic_to_shared(rowbuf[0]),
                        (uint32_t)__cvta_generic_to_shared(rowbuf[1]) };
    uint32_t s_we = (uint32_t)__cvta_generic_to_shared(we);

    const float hwb = g_hw[b];
    const float bev = be[0];

    auto issue = [&](int st) {
        uint32_t dst = srb[st & 1];
        int s0 = chunk * 16 + st * 4;
        for (int i = tid; i < 4 * (TWOH / 4); i += 256) {
            int r = i >> 9, c = i & 511;
            cpa16(dst + (r * 512 + c) * 16,
                  (const float4*)(enc + ((size_t)(s0 + r) * BB + b) * TWOH) + c);
        }
        cpa_commit();
    };

    // group 0: we + stage 0
    for (int i = tid; i < TWOH / 4; i += 256)
        cpa16(s_we + i * 16, (const float4*)(Wen + HH) + i);
    issue(0);

    float ctx[8];
#pragma unroll
    for (int i = 0; i < 8; i++) ctx[i] = 0.f;
    float M = -1e30f, L = 0.f;

#pragma unroll
    for (int st = 0; st < 4; st++) {
        if (st < 3) issue(st + 1);
        if (st < 3) cpa_wait1(); else cpa_wait0();
        __syncthreads();
        const float* rows = rowbuf[st & 1];

        // energy: 2 warps per row (each half of 2048 features)
        {
            int r = w & 3, h = w >> 2;
            const float* row = rows + r * TWOH + h * 1024;
            const float* wv  = we + h * 1024;
            float p = 0.f;
            for (int j = lane; j < 1024; j += 32) p += row[j] * wv[j];
            for (int o = 16; o; o >>= 1) p += __shfl_xor_sync(~0u, p, o);
            if (lane == 0) sEp[w] = p;
        }
        __syncthreads();

        float E[4], m2 = M;
#pragma unroll
        for (int i = 0; i < 4; i++) {
            E[i] = fmaxf(sEp[i] + sEp[i + 4] + hwb + bev, 0.f);
            m2 = fmaxf(m2, E[i]);
        }
        float pe[4], lst = 0.f;
#pragma unroll
        for (int i = 0; i < 4; i++) { pe[i] = __expf(E[i] - m2); lst += pe[i]; }
        float scale = __expf(M - m2);
        L = L * scale + lst;
        M = m2;
#pragma unroll
        for (int q = 0; q < 8; q++) {
            int d = q * 256 + tid;
            float v = ctx[q] * scale;
#pragma unroll
            for (int i = 0; i < 4; i++) v += pe[i] * rows[i * TWOH + d];
            ctx[q] = v;
        }
        __syncthreads();   // buffer + sEp reuse barrier
    }

    float* dst = g_ctx + ((size_t)b * NCHUNK + chunk) * TWOH;
#pragma unroll
    for (int q = 0; q < 8; q++) dst[q * 256 + tid] = ctx[q];
    if (tid == 0) { g_eM[b * NCHUNK + chunk] = M; g_eL[b * NCHUNK + chunk] = L; }
}

// ---------------- K2: combine (8-way parallel over features) ----------------
__global__ void k_combine(const float* __restrict__ emb_table,
                          const int* __restrict__ x,
                          const float* __restrict__ hidden) {
    int b = blockIdx.x, y = blockIdx.y, tid = threadIdx.x;
    __shared__ float ssc[NCHUNK];
    __shared__ float sInv;
    if (tid == 0) {
        float M = -1e30f;
        for (int i = 0; i < NCHUNK; i++) M = fmaxf(M, g_eM[b * NCHUNK + i]);
        float L = 0.f;
        for (int i = 0; i < NCHUNK; i++) {
            float s = __expf(g_eM[b * NCHUNK + i] - M);
            ssc[i] = s;
            L += s * g_eL[b * NCHUNK + i];
        }
        sInv = 1.f / L;
    }
    __syncthreads();
    float inv = sInv;
    unsigned short hi, lo;
    {
        int d = y * 256 + tid;
        float v = 0.f;
#pragma unroll 8
        for (int i = 0; i < NCHUNK; i++)
            v += ssc[i] * g_ctx[((size_t)b * NCHUNK + i) * TWOH + d];
        split16(v * inv, hi, lo);
        g_Bhi[b * KTOT + d] = hi; g_Blo[b * KTOT + d] = lo;
    }
    int xb = x[b];
    if (tid < 64) {
        int j = y * 64 + tid;
        split16(emb_table[(size_t)xb * EE + j], hi, lo);
        g_Bhi[b * KTOT + TWOH + j] = hi; g_Blo[b * KTOT + TWOH + j] = lo;
    }
    if (tid < 128) {
        int j = y * 128 + tid;
        split16(hidden[b * HH + j], hi, lo);
        g_Bhi[b * KTOT + TWOH + EE + j] = hi; g_Blo[b * KTOT + TWOH + EE + j] = lo;
    }
}

// ================= MT=128 GEMM pieces (gates, R10-proven) ======================
__device__ __forceinline__ void stsA128(uint32_t sb, const float4* pa, int cm, int ckq) {
    uint32_t h[8], lw[8];
#pragma unroll
    for (int i = 0; i < 4; i++) {
        uint32_t bx = __float_as_uint(pa[i].x), by = __float_as_uint(pa[i].y);
        uint32_t bz = __float_as_uint(pa[i].z), bw = __float_as_uint(pa[i].w);
        h[2 * i]     = __byte_perm(bx, by, 0x7632);
        h[2 * i + 1] = __byte_perm(bz, bw, 0x7632);
        float lx = pa[i].x - __uint_as_float(bx & 0xFFFF0000u);
        float ly = pa[i].y - __uint_as_float(by & 0xFFFF0000u);
        float lz = pa[i].z - __uint_as_float(bz & 0xFFFF0000u);
        float lv = pa[i].w - __uint_as_float(bw & 0xFFFF0000u);
        lw[2 * i]     = __byte_perm(__float_as_uint(lx), __float_as_uint(ly), 0x7632);
        lw[2 * i + 1] = __byte_perm(__float_as_uint(lz), __float_as_uint(lv), 0x7632);
    }
    uint32_t d = sb + G_AHI + cm * 80 + ckq * 2;
    st4(d, h[0], h[1], h[2], h[3]);
    st4(d + 16, h[4], h[5], h[6], h[7]);
    d = sb + G_ALO + cm * 80 + ckq * 2;
    st4(d, lw[0], lw[1], lw[2], lw[3]);
    st4(d + 16, lw[4], lw[5], lw[6], lw[7]);
}

__device__ __forceinline__ void domma128(uint32_t sb, float (*acc)[4], int w, int l) {
    const int arow = w * 16 + (l & 7) + ((l >> 3) & 1) * 8;
    const int acol = ((l >> 4) & 1) * 8;
    const int brof = ((l >> 4) & 1) * 8 + (l & 7);
    const int bcol = ((l >> 3) & 1) * 8;
#pragma unroll
    for (int ks = 0; ks < 2; ks++) {
        uint32_t ahi[4], alo[4];
        uint32_t ao = arow * 80 + (ks * 16 + acol) * 2;
        ldsm4(ahi, sb + G_AHI + ao);
        ldsm4(alo, sb + G_ALO + ao);
#pragma unroll
        for (int p = 0; p < 4; p++) {
            uint32_t bh[4], bl[4];
            uint32_t bo = (p * 16 + brof) * 80 + (ks * 16 + bcol) * 2;
            ldsm4(bh, sb + G_BHI + bo);
            ldsm4(bl, sb + G_BLO + bo);
            mma16816(acc[2 * p],     ahi, bh);
            mma16816(acc[2 * p + 1], ahi, bh + 2);
            mma16816(acc[2 * p],     alo, bh);
            mma16816(acc[2 * p + 1], alo, bh + 2);
            mma16816(acc[2 * p],     ahi, bl);
            mma16816(acc[2 * p + 1], ahi, bl + 2);
        }
    }
}

// ---------------- K3: gates GEMM  grid(32, 14), MT=128 ------------------------
__global__ __launch_bounds__(256, 3)
void k_gates_mm(const float* __restrict__ Wih, const float* __restrict__ Whh) {
    extern __shared__ char dsm[];
    uint32_t base = (uint32_t)__cvta_generic_to_shared(dsm);
    const int tid = threadIdx.x, w = tid >> 5, l = tid & 31;
    const int mbase = blockIdx.x * GMT;
    const int split = blockIdx.y;
    const int kstart = split * KSPLIT;
    const int NCH = KSPLIT / KC;     // 8

    const int cm = tid >> 1, ckq = (tid & 1) * 16;
    const int bn = tid >> 2, bq = (tid & 3) * 16;

    float acc[8][4];
#pragma unroll
    for (int i = 0; i < 8; i++)
#pragma unroll
        for (int j = 0; j < 4; j++) acc[i][j] = 0.f;

    float4 pa[4];
    auto ldgA = [&](int kg) {
        const float* src = (kg < 2560)
            ? Wih + (size_t)(mbase + cm) * 2560 + kg
            : Whh + (size_t)(mbase + cm) * 1024 + (kg - 2560);
#pragma unroll
        for (int i = 0; i < 4; i++) pa[i] = *(const float4*)(src + ckq + i * 4);
    };
    auto cpaB = [&](int kg, uint32_t sb) {
        cpa16(sb + G_BHI + bn * 80 + bq, (const char*)g_Bhi + (size_t)bn * KTOT * 2 + kg * 2 + bq);
        cpa16(sb + G_BLO + bn * 80 + bq, (const char*)g_Blo + (size_t)bn * KTOT * 2 + kg * 2 + bq);
        cpa_commit();
    };

    ldgA(kstart);
    cpaB(kstart, base);
    for (int c = 0; c < NCH; c++) {
        uint32_t sb = base + (c & 1) * G_STAGE;
        stsA128(sb, pa, cm, ckq);
        cpa_wait0();
        __syncthreads();
        if (c + 1 < NCH) {
            int kg = kstart + (c + 1) * KC;
            ldgA(kg);
            cpaB(kg, base + ((c + 1) & 1) * G_STAGE);
        }
        domma128(sb, acc, w, l);
        __syncthreads();
    }

    const int gid = l >> 2, tig = (l & 3) * 2;
    float* outp = g_gatesP + ((size_t)split * G4 + mbase + w * 16) * BB;
#pragma unroll
    for (int no = 0; no < 8; no++) {
        *(float2*)(outp + gid * BB + no * 8 + tig)       = make_float2(acc[no][0], acc[no][1]);
        *(float2*)(outp + (gid + 8) * BB + no * 8 + tig) = make_float2(acc[no][2], acc[no][3]);
    }
}

// ---------------- K3b: LSTM ---------------------------------------------------
__global__ void k_lstm(const float* __restrict__ b_ih, const float* __restrict__ b_hh,
                       const float* __restrict__ cell,
                       float* __restrict__ h1o, float* __restrict__ c1o) {
    int idx = blockIdx.x * blockDim.x + threadIdx.x;
    int b = idx & 63, j = idx >> 6;
    float gi = 0, gf = 0, gg = 0, go = 0;
#pragma unroll
    for (int s = 0; s < NSPLIT; s++) {
        const float* gp = g_gatesP + (size_t)s * G4 * BB;
        gi += gp[(j) * BB + b];
        gf += gp[(1024 + j) * BB + b];
        gg += gp[(2048 + j) * BB + b];
        go += gp[(3072 + j) * BB + b];
    }
    gi += b_ih[j]        + b_hh[j];
    gf += b_ih[1024 + j] + b_hh[1024 + j];
    gg += b_ih[2048 + j] + b_hh[2048 + j];
    go += b_ih[3072 + j] + b_hh[3072 + j];
    float c0 = cell[b * HH + j];
    float c1 = sigm(gf) * c0 + sigm(gi) * tanhf(gg);
    float h1 = sigm(go) * tanhf(c1);
    h1o[b * HH + j] = h1;
    c1o[b * HH + j] = c1;
    unsigned short hi, lo;
    split16(h1, hi, lo);
    g_h1hi[b * HH + j] = hi;
    g_h1lo[b * HH + j] = lo;
}

// ================= MT=64 / KC=64 GEMM pieces (fc) ==============================
__device__ __forceinline__ void stsA64(uint32_t sb, const float4* pa, int row, int q16) {
    uint32_t h[8], lw[8];
#pragma unroll
    for (int i = 0; i < 4; i++) {
        uint32_t bx = __float_as_uint(pa[i].x), by = __float_as_uint(pa[i].y);
        uint32_t bz = __float_as_uint(pa[i].z), bw = __float_as_uint(pa[i].w);
        h[2 * i]     = __byte_perm(bx, by, 0x7632);
        h[2 * i + 1] = __byte_perm(bz, bw, 0x7632);
        float lx = pa[i].x - __uint_as_float(bx & 0xFFFF0000u);
        float ly = pa[i].y - __uint_as_float(by & 0xFFFF0000u);
        float lz = pa[i].z - __uint_as_float(bz & 0xFFFF0000u);
        float lv = pa[i].w - __uint_as_float(bw & 0xFFFF0000u);
        lw[2 * i]     = __byte_perm(__float_as_uint(lx), __float_as_uint(ly), 0x7632);
        lw[2 * i + 1] = __byte_perm(__float_as_uint(lz), __float_as_uint(lv), 0x7632);
    }
    uint32_t d = sb + F_AHI + row * 144 + q16 * 2;
    st4(d, h[0], h[1], h[2], h[3]);
    st4(d + 16, h[4], h[5], h[6], h[7]);
    d = sb + F_ALO + row * 144 + q16 * 2;
    st4(d, lw[0], lw[1], lw[2], lw[3]);
    st4(d + 16, lw[4], lw[5], lw[6], lw[7]);
}

__device__ __forceinline__ void domma64(uint32_t sb, float (*acc)[4], int w, int l) {
    const int wq = w & 3, wh = w >> 2;
    const int arow = wq * 16 + (l & 7) + ((l >> 3) & 1) * 8;
    const int acol = ((l >> 4) & 1) * 8;
    const int brof = wh * 32 + ((l >> 4) & 1) * 8 + (l & 7);
    const int bcol = ((l >> 3) & 1) * 8;
#pragma unroll
    for (int ks = 0; ks < 4; ks++) {
        uint32_t ahi[4], alo[4];
        uint32_t ao = arow * 144 + (ks * 16 + acol) * 2;
        ldsm4(ahi, sb + F_AHI + ao);
        ldsm4(alo, sb + F_ALO + ao);
#pragma unroll
        for (int p = 0; p < 2; p++) {
            uint32_t bh[4], bl[4];
            uint32_t bo = (p * 16 + brof) * 144 + (ks * 16 + bcol) * 2;
            ldsm4(bh, sb + F_BHI + bo);
            ldsm4(bl, sb + F_BLO + bo);
            mma16816(acc[2 * p],     ahi, bh);
            mma16816(acc[2 * p + 1], ahi, bh + 2);
            mma16816(acc[2 * p],     alo, bh);
            mma16816(acc[2 * p + 1], alo, bh + 2);
            mma16816(acc[2 * p],     ahi, bl);
            mma16816(acc[2 * p + 1], ahi, bl + 2);
        }
    }
}

// ---------------- K4: FC GEMM  grid(500), K=1024, MT=64 KC=64 -----------------
__global__ __launch_bounds__(256, 3)
void k_fc_mm(const float* __restrict__ Wfc, const float* __restrict__ bfc,
             float* __restrict__ pred) {
    extern __shared__ char dsm[];
    uint32_t base = (uint32_t)__cvta_generic_to_shared(dsm);
    const int tid = threadIdx.x, w = tid >> 5, l = tid & 31;
    const int mbase = blockIdx.x * FMT;
    const int NCH = HH / FKC;        // 16

    const int arow = tid >> 2, aq16 = (tid & 3) * 16;
    const int bn = tid >> 2, bq = (tid & 3) * 32;

    float acc[4][4];
#pragma unroll
    for (int i = 0; i < 4; i++)
#pragma unroll
        for (int j = 0; j < 4; j++) acc[i][j] = 0.f;

    float4 pa[4];
    auto ldgA = [&](int kg) {
        const float* src = Wfc + (size_t)(mbase + arow) * HH + kg + aq16;
#pragma unroll
        for (int i = 0; i < 4; i++) pa[i] = *(const float4*)(src + i * 4);
    };
    auto cpaB = [&](int kg, uint32_t sb) {
        const char* ph = (const char*)g_h1hi + (size_t)bn * HH * 2 + kg * 2 + bq;
        const char* pl = (const char*)g_h1lo + (size_t)bn * HH * 2 + kg * 2 + bq;
        cpa16(sb + F_BHI + bn * 144 + bq,      ph);
        cpa16(sb + F_BHI + bn * 144 + bq + 16, ph + 16);
        cpa16(sb + F_BLO + bn * 144 + bq,      pl);
        cpa16(sb + F_BLO + bn * 144 + bq + 16, pl + 16);
        cpa_commit();
    };

    ldgA(0);
    cpaB(0, base);
    for (int c = 0; c < NCH; c++) {
        uint32_t sb = base + (c & 1) * F_STAGE;
        stsA64(sb, pa, arow, aq16);
        cpa_wait0();
        __syncthreads();
        if (c + 1 < NCH) {
            int kg = (c + 1) * FKC;
            ldgA(kg);
            cpaB(kg, base + ((c + 1) & 1) * F_STAGE);
        }
        domma64(sb, acc, w, l);
        __syncthreads();
    }
    __syncthreads();

    float* ts = (float*)dsm;      // [64][68]
    const int wq = w & 3, wh = w >> 2;
    const int gid = l >> 2, tig = (l & 3) * 2;
    float bias0 = bfc[mbase + wq * 16 + gid];
    float bias1 = bfc[mbase + wq * 16 + gid + 8];
#pragma unroll
    for (int j = 0; j < 4; j++) {
        int n = wh * 32 + j * 8 + tig;
        ts[n * 68 + wq * 16 + gid]           = acc[j][0] + bias0;
        ts[(n + 1) * 68 + wq * 16 + gid]     = acc[j][1] + bias0;
        ts[n * 68 + wq * 16 + gid + 8]       = acc[j][2] + bias1;
        ts[(n + 1) * 68 + wq * 16 + gid + 8] = acc[j][3] + bias1;
    }
    __syncthreads();
    {
        int b = tid >> 2, q = tid & 3;
        const float* srow = ts + b * 68 + q * 16;
        float* drow = pred + (size_t)b * VV + mbase + q * 16;
#pragma unroll
        for (int i = 0; i < 4; i++)
            *(float4*)(drow + i * 4) = make_float4(srow[i * 4], srow[i * 4 + 1],
                                                   srow[i * 4 + 2], srow[i * 4 + 3]);
    }
}

// ---------------- launch --------------------------------------------------------
extern "C" void kernel_launch(void* const* d_in, const int* in_sizes, int n_in,
                              void* d_out, int out_size) {
    const int*   x       = (const int*)  d_in[0];
    const float* enc     = (const float*)d_in[1];
    const float* hidden  = (const float*)d_in[2];
    const float* cell    = (const float*)d_in[3];
    const float* emb     = (const float*)d_in[4];
    const float* Wen     = (const float*)d_in[5];
    const float* be      = (const float*)d_in[6];
    const float* Wih     = (const float*)d_in[7];
    const float* Whh     = (const float*)d_in[8];
    const float* b_ih    = (const float*)d_in[9];
    const float* b_hh    = (const float*)d_in[10];
    const float* Wfc     = (const float*)d_in[11];
    const float* bfc     = (const float*)d_in[12];

    float* pred = (float*)d_out;
    float* h1o  = pred + (size_t)BB * VV;
    float* c1o  = h1o + (size_t)BB * HH;

    const int smem_attn = (8 * TWOH + TWOH) * sizeof(float);       // 73728
    cudaFuncSetAttribute(k_attn, cudaFuncAttributeMaxDynamicSharedMemorySize, smem_attn);
    cudaFuncSetAttribute(k_gates_mm, cudaFuncAttributeMaxDynamicSharedMemorySize, 2 * G_STAGE);
    cudaFuncSetAttribute(k_fc_mm, cudaFuncAttributeMaxDynamicSharedMemorySize, 2 * F_STAGE);

    k_hw<<<BB, 128>>>(hidden, Wen);
    k_attn<<<dim3(NCHUNK, BB), 256, smem_attn>>>(enc, Wen, be);
    k_combine<<<dim3(BB, 8), 256>>>(emb, x, hidden);
    k_gates_mm<<<dim3(G4 / GMT, NSPLIT), 256, 2 * G_STAGE>>>(Wih, Whh);
    k_lstm<<<(BB * HH) / 256, 256>>>(b_ih, b_hh, cell, h1o, c1o);
    k_fc_mm<<<VV / FMT, 256, 2 * F_STAGE>>>(Wfc, bfc, pred);
}

// round 15
// speedup vs baseline: 1.0868x; 1.0868x over previous
#include <cuda_runtime.h>
#include <cstdint>

#define SS 512
#define BB 64
#define HH 1024
#define EE 512
#define VV 32000
#define TWOH 2048
#define KTOT 3584
#define G4 4096
#define NCHUNK 32           // 32 chunks of 16 rows (2 stages of 8)
#define CROWS 8
#define NSPLIT 14
#define KSPLIT 256

// gates GEMM: MT=128 (R10-proven)
#define GMT 128
#define KC 32
#define G_AHI 0
#define G_ALO 10240
#define G_BHI 20480
#define G_BLO 25600
#define G_STAGE 30720
// fc GEMM: MT=64 (R12-proven)
#define FMT 64
#define F_AHI 0
#define F_ALO 5120
#define F_BHI 10240
#define F_BLO 15360
#define F_STAGE 20480

// ---------------- scratch ----------------------------------------------------
__device__ float g_hw[BB];
__device__ float g_eM[BB * NCHUNK];
__device__ float g_eL[BB * NCHUNK];
__device__ float g_ctx[(size_t)BB * NCHUNK * TWOH];
__device__ unsigned short g_Bhi[BB * KTOT];
__device__ unsigned short g_Blo[BB * KTOT];
__device__ unsigned short g_h1hi[BB * HH];
__device__ unsigned short g_h1lo[BB * HH];
__device__ float g_gatesP[NSPLIT * G4 * BB];  // [s][m][b]

__device__ __forceinline__ float sigm(float x) { return 1.f / (1.f + __expf(-x)); }

__device__ __forceinline__ void cpa16(uint32_t s, const void* g) {
    asm volatile("cp.async.cg.shared.global [%0], [%1], 16;" :: "r"(s), "l"(g));
}
__device__ __forceinline__ void cpa_commit() { asm volatile("cp.async.commit_group;"); }
__device__ __forceinline__ void cpa_wait0()  { asm volatile("cp.async.wait_group 0;"); }
__device__ __forceinline__ void cpa_wait1()  { asm volatile("cp.async.wait_group 1;"); }

__device__ __forceinline__ void ldsm4(uint32_t* r, uint32_t addr) {
    asm volatile("ldmatrix.sync.aligned.m8n8.x4.shared.b16 {%0,%1,%2,%3}, [%4];"
        : "=r"(r[0]), "=r"(r[1]), "=r"(r[2]), "=r"(r[3]) : "r"(addr));
}
__device__ __forceinline__ void mma16816(float* d, const uint32_t* a, const uint32_t* b) {
    asm volatile("mma.sync.aligned.m16n8k16.row.col.f32.bf16.bf16.f32 "
        "{%0,%1,%2,%3},{%4,%5,%6,%7},{%8,%9},{%0,%1,%2,%3};"
        : "+f"(d[0]), "+f"(d[1]), "+f"(d[2]), "+f"(d[3])
        : "r"(a[0]), "r"(a[1]), "r"(a[2]), "r"(a[3]), "r"(b[0]), "r"(b[1]));
}
__device__ __forceinline__ void st4(uint32_t a, uint32_t x, uint32_t y, uint32_t z, uint32_t w) {
    asm volatile("st.shared.v4.u32 [%0], {%1,%2,%3,%4};" :: "r"(a), "r"(x), "r"(y), "r"(z), "r"(w));
}

__device__ __forceinline__ void split16(float x, unsigned short& hi, unsigned short& lo) {
    uint32_t bx = __float_as_uint(x);
    hi = (unsigned short)(bx >> 16);
    float lf = x - __uint_as_float(bx & 0xFFFF0000u);
    lo = (unsigned short)(__float_as_uint(lf) >> 16);
}

// ---------------- K0 ----------------------------------------------------------
__global__ void k_hw(const float* __restrict__ hidden, const float* __restrict__ Wen) {
    int b = blockIdx.x, tid = threadIdx.x;
    float p = 0.f;
    for (int k = tid; k < HH; k += 128) p += hidden[b * HH + k] * Wen[k];
    __shared__ float red[128];
    red[tid] = p; __syncthreads();
    for (int o = 64; o >= 32; o >>= 1) { if (tid < o) red[tid] += red[tid + o]; __syncthreads(); }
    if (tid < 32) {
        float v = red[tid];
        for (int o = 16; o; o >>= 1) v += __shfl_xor_sync(~0u, v, o);
        if (tid == 0) g_hw[b] = v;
    }
}

// ---------------- K1: attention (16 rows per CTA, 2 stages, online softmax) ---
__global__ __launch_bounds__(256)
void k_attn(const float* __restrict__ enc, const float* __restrict__ Wen,
            const float* __restrict__ be) {
    extern __shared__ float sm[];
    float* rows = sm;                 // [8][2048]
    float* we   = sm + CROWS * TWOH;  // [2048]
    __shared__ float sE[CROWS];
    const int chunk = blockIdx.x, b = blockIdx.y, tid = threadIdx.x;
    const int w = tid >> 5, lane = tid & 31;
    uint32_t s_rows = (uint32_t)__cvta_generic_to_shared(rows);
    uint32_t s_we   = (uint32_t)__cvta_generic_to_shared(we);

    for (int i = tid; i < TWOH / 4; i += 256)
        cpa16(s_we + i * 16, (const float4*)(Wen + HH) + i);

    float ctx[8];
#pragma unroll
    for (int i = 0; i < 8; i++) ctx[i] = 0.f;
    float M = -1e30f, L = 0.f;

    const float hwb = g_hw[b];
    const float bev = be[0];

#pragma unroll
    for (int st = 0; st < 2; st++) {
        const int s0 = chunk * 16 + st * CROWS;
        for (int i = tid; i < CROWS * (TWOH / 4); i += 256) {
            int r = i >> 9, c = i & 511;
            cpa16(s_rows + (r * (TWOH / 4) + c) * 16,
                  (const float4*)(enc + ((size_t)(s0 + r) * BB + b) * TWOH) + c);
        }
        cpa_commit(); cpa_wait0();
        __syncthreads();

        {
            float p = 0.f;
            const float* row = rows + w * TWOH;
            for (int j = lane; j < TWOH; j += 32) p += row[j] * we[j];
            for (int o = 16; o; o >>= 1) p += __shfl_xor_sync(~0u, p, o);
            if (lane == 0) sE[w] = fmaxf(p + hwb + bev, 0.f);
        }
        __syncthreads();

        float m2 = M;
#pragma unroll
        for (int i = 0; i < CROWS; i++) m2 = fmaxf(m2, sE[i]);
        float pe[CROWS];
        float lst = 0.f;
#pragma unroll
        for (int i = 0; i < CROWS; i++) { pe[i] = __expf(sE[i] - m2); lst += pe[i]; }
        float scale = __expf(M - m2);
        L = L * scale + lst;
        M = m2;
#pragma unroll
        for (int q = 0; q < 8; q++) {
            int d = q * 256 + tid;
            float v = ctx[q] * scale;
#pragma unroll
            for (int i = 0; i < CROWS; i++) v += pe[i] * rows[i * TWOH + d];
            ctx[q] = v;
        }
        if (st == 0) __syncthreads();
    }

    float* dst = g_ctx + ((size_t)b * NCHUNK + chunk) * TWOH;
#pragma unroll
    for (int q = 0; q < 8; q++) dst[q * 256 + tid] = ctx[q];
    if (tid == 0) { g_eM[b * NCHUNK + chunk] = M; g_eL[b * NCHUNK + chunk] = L; }
}

// ---------------- K2: combine (8-way parallel over features) ----------------
__global__ void k_combine(const float* __restrict__ emb_table,
                          const int* __restrict__ x,
                          const float* __restrict__ hidden) {
    int b = blockIdx.x, y = blockIdx.y, tid = threadIdx.x;
    __shared__ float ssc[NCHUNK];
    __shared__ float sInv;
    if (tid == 0) {
        float M = -1e30f;
        for (int i = 0; i < NCHUNK; i++) M = fmaxf(M, g_eM[b * NCHUNK + i]);
        float L = 0.f;
        for (int i = 0; i < NCHUNK; i++) {
            float s = __expf(g_eM[b * NCHUNK + i] - M);
            ssc[i] = s;
            L += s * g_eL[b * NCHUNK + i];
        }
        sInv = 1.f / L;
    }
    __syncthreads();
    float inv = sInv;
    unsigned short hi, lo;
    {
        int d = y * 256 + tid;
        float v = 0.f;
#pragma unroll 8
        for (int i = 0; i < NCHUNK; i++)
            v += ssc[i] * g_ctx[((size_t)b * NCHUNK + i) * TWOH + d];
        split16(v * inv, hi, lo);
        g_Bhi[b * KTOT + d] = hi; g_Blo[b * KTOT + d] = lo;
    }
    int xb = x[b];
    if (tid < 64) {
        int j = y * 64 + tid;
        split16(emb_table[(size_t)xb * EE + j], hi, lo);
        g_Bhi[b * KTOT + TWOH + j] = hi; g_Blo[b * KTOT + TWOH + j] = lo;
    }
    if (tid < 128) {
        int j = y * 128 + tid;
        split16(hidden[b * HH + j], hi, lo);
        g_Bhi[b * KTOT + TWOH + EE + j] = hi; g_Blo[b * KTOT + TWOH + EE + j] = lo;
    }
}

// ================= MT=128 GEMM pieces (gates) ==================================
__device__ __forceinline__ void stsA128(uint32_t sb, const float4* pa, int cm, int ckq) {
    uint32_t h[8], lw[8];
#pragma unroll
    for (int i = 0; i < 4; i++) {
        uint32_t bx = __float_as_uint(pa[i].x), by = __float_as_uint(pa[i].y);
        uint32_t bz = __float_as_uint(pa[i].z), bw = __float_as_uint(pa[i].w);
        h[2 * i]     = __byte_perm(bx, by, 0x7632);
        h[2 * i + 1] = __byte_perm(bz, bw, 0x7632);
        float lx = pa[i].x - __uint_as_float(bx & 0xFFFF0000u);
        float ly = pa[i].y - __uint_as_float(by & 0xFFFF0000u);
        float lz = pa[i].z - __uint_as_float(bz & 0xFFFF0000u);
        float lv = pa[i].w - __uint_as_float(bw & 0xFFFF0000u);
        lw[2 * i]     = __byte_perm(__float_as_uint(lx), __float_as_uint(ly), 0x7632);
        lw[2 * i + 1] = __byte_perm(__float_as_uint(lz), __float_as_uint(lv), 0x7632);
    }
    uint32_t d = sb + G_AHI + cm * 80 + ckq * 2;
    st4(d, h[0], h[1], h[2], h[3]);
    st4(d + 16, h[4], h[5], h[6], h[7]);
    d = sb + G_ALO + cm * 80 + ckq * 2;
    st4(d, lw[0], lw[1], lw[2], lw[3]);
    st4(d + 16, lw[4], lw[5], lw[6], lw[7]);
}

__device__ __forceinline__ void domma128(uint32_t sb, float (*acc)[4], int w, int l) {
    const int arow = w * 16 + (l & 7) + ((l >> 3) & 1) * 8;
    const int acol = ((l >> 4) & 1) * 8;
    const int brof = ((l >> 4) & 1) * 8 + (l & 7);
    const int bcol = ((l >> 3) & 1) * 8;
#pragma unroll
    for (int ks = 0; ks < 2; ks++) {
        uint32_t ahi[4], alo[4];
        uint32_t ao = arow * 80 + (ks * 16 + acol) * 2;
        ldsm4(ahi, sb + G_AHI + ao);
        ldsm4(alo, sb + G_ALO + ao);
#pragma unroll
        for (int p = 0; p < 4; p++) {
            uint32_t bh[4], bl[4];
            uint32_t bo = (p * 16 + brof) * 80 + (ks * 16 + bcol) * 2;
            ldsm4(bh, sb + G_BHI + bo);
            ldsm4(bl, sb + G_BLO + bo);
            mma16816(acc[2 * p],     ahi, bh);
            mma16816(acc[2 * p + 1], ahi, bh + 2);
            mma16816(acc[2 * p],     alo, bh);
            mma16816(acc[2 * p + 1], alo, bh + 2);
            mma16816(acc[2 * p],     ahi, bl);
            mma16816(acc[2 * p + 1], ahi, bl + 2);
        }
    }
}

// ---------------- K3: gates GEMM  grid(32, 14), MT=128 ------------------------
__global__ __launch_bounds__(256, 3)
void k_gates_mm(const float* __restrict__ Wih, const float* __restrict__ Whh) {
    extern __shared__ char dsm[];
    uint32_t base = (uint32_t)__cvta_generic_to_shared(dsm);
    const int tid = threadIdx.x, w = tid >> 5, l = tid & 31;
    const int mbase = blockIdx.x * GMT;
    const int split = blockIdx.y;
    const int kstart = split * KSPLIT;
    const int NCH = KSPLIT / KC;     // 8

    const int cm = tid >> 1, ckq = (tid & 1) * 16;
    const int bn = tid >> 2, bq = (tid & 3) * 16;

    float acc[8][4];
#pragma unroll
    for (int i = 0; i < 8; i++)
#pragma unroll
        for (int j = 0; j < 4; j++) acc[i][j] = 0.f;

    float4 pa[4];
    auto ldgA = [&](int kg) {
        const float* src = (kg < 2560)
            ? Wih + (size_t)(mbase + cm) * 2560 + kg
            : Whh + (size_t)(mbase + cm) * 1024 + (kg - 2560);
#pragma unroll
        for (int i = 0; i < 4; i++) pa[i] = *(const float4*)(src + ckq + i * 4);
    };
    auto cpaB = [&](int kg, uint32_t sb) {
        cpa16(sb + G_BHI + bn * 80 + bq, (const char*)g_Bhi + (size_t)bn * KTOT * 2 + kg * 2 + bq);
        cpa16(sb + G_BLO + bn * 80 + bq, (const char*)g_Blo + (size_t)bn * KTOT * 2 + kg * 2 + bq);
        cpa_commit();
    };

    ldgA(kstart);
    cpaB(kstart, base);
    for (int c = 0; c < NCH; c++) {
        uint32_t sb = base + (c & 1) * G_STAGE;
        stsA128(sb, pa, cm, ckq);
        // early-issue next chunk's loads (pa dead; stage (c+1)&1 free since sync)
        if (c + 1 < NCH) {
            int kg = kstart + (c + 1) * KC;
            ldgA(kg);
            cpaB(kg, base + ((c + 1) & 1) * G_STAGE);
            cpa_wait1();            // chunk c's B group complete; c+1 in flight
        } else {
            cpa_wait0();
        }
        __syncthreads();
        domma128(sb, acc, w, l);
        __syncthreads();
    }

    const int gid = l >> 2, tig = (l & 3) * 2;
    float* outp = g_gatesP + ((size_t)split * G4 + mbase + w * 16) * BB;
#pragma unroll
    for (int no = 0; no < 8; no++) {
        *(float2*)(outp + gid * BB + no * 8 + tig)       = make_float2(acc[no][0], acc[no][1]);
        *(float2*)(outp + (gid + 8) * BB + no * 8 + tig) = make_float2(acc[no][2], acc[no][3]);
    }
}

// ---------------- K3b: LSTM ---------------------------------------------------
__global__ void k_lstm(const float* __restrict__ b_ih, const float* __restrict__ b_hh,
                       const float* __restrict__ cell,
                       float* __restrict__ h1o, float* __restrict__ c1o) {
    int idx = blockIdx.x * blockDim.x + threadIdx.x;
    int b = idx & 63, j = idx >> 6;
    float gi = 0, gf = 0, gg = 0, go = 0;
#pragma unroll
    for (int s = 0; s < NSPLIT; s++) {
        const float* gp = g_gatesP + (size_t)s * G4 * BB;
        gi += gp[(j) * BB + b];
        gf += gp[(1024 + j) * BB + b];
        gg += gp[(2048 + j) * BB + b];
        go += gp[(3072 + j) * BB + b];
    }
    gi += b_ih[j]        + b_hh[j];
    gf += b_ih[1024 + j] + b_hh[1024 + j];
    gg += b_ih[2048 + j] + b_hh[2048 + j];
    go += b_ih[3072 + j] + b_hh[3072 + j];
    float c0 = cell[b * HH + j];
    float c1 = sigm(gf) * c0 + sigm(gi) * tanhf(gg);
    float h1 = sigm(go) * tanhf(c1);
    h1o[b * HH + j] = h1;
    c1o[b * HH + j] = c1;
    unsigned short hi, lo;
    split16(h1, hi, lo);
    g_h1hi[b * HH + j] = hi;
    g_h1lo[b * HH + j] = lo;
}

// ================= MT=64 GEMM pieces (fc) ======================================
__device__ __forceinline__ void stsA64(uint32_t sb, const float4* pa, int row, int qq) {
    uint32_t h[4], lw[4];
#pragma unroll
    for (int i = 0; i < 2; i++) {
        uint32_t bx = __float_as_uint(pa[i].x), by = __float_as_uint(pa[i].y);
        uint32_t bz = __float_as_uint(pa[i].z), bw = __float_as_uint(pa[i].w);
        h[2 * i]     = __byte_perm(bx, by, 0x7632);
        h[2 * i + 1] = __byte_perm(bz, bw, 0x7632);
        float lx = pa[i].x - __uint_as_float(bx & 0xFFFF0000u);
        float ly = pa[i].y - __uint_as_float(by & 0xFFFF0000u);
        float lz = pa[i].z - __uint_as_float(bz & 0xFFFF0000u);
        float lv = pa[i].w - __uint_as_float(bw & 0xFFFF0000u);
        lw[2 * i]     = __byte_perm(__float_as_uint(lx), __float_as_uint(ly), 0x7632);
        lw[2 * i + 1] = __byte_perm(__float_as_uint(lz), __float_as_uint(lv), 0x7632);
    }
    uint32_t d = sb + F_AHI + row * 80 + qq * 2;
    st4(d, h[0], h[1], h[2], h[3]);
    d = sb + F_ALO + row * 80 + qq * 2;
    st4(d, lw[0], lw[1], lw[2], lw[3]);
}

__device__ __forceinline__ void domma64(uint32_t sb, float (*acc)[4], int w, int l) {
    const int wq = w & 3, wh = w >> 2;
    const int arow = wq * 16 + (l & 7) + ((l >> 3) & 1) * 8;
    const int acol = ((l >> 4) & 1) * 8;
    const int brof = wh * 32 + ((l >> 4) & 1) * 8 + (l & 7);
    const int bcol = ((l >> 3) & 1) * 8;
#pragma unroll
    for (int ks = 0; ks < 2; ks++) {
        uint32_t ahi[4], alo[4];
        uint32_t ao = arow * 80 + (ks * 16 + acol) * 2;
        ldsm4(ahi, sb + F_AHI + ao);
        ldsm4(alo, sb + F_ALO + ao);
#pragma unroll
        for (int p = 0; p < 2; p++) {
            uint32_t bh[4], bl[4];
            uint32_t bo = (p * 16 + brof) * 80 + (ks * 16 + bcol) * 2;
            ldsm4(bh, sb + F_BHI + bo);
            ldsm4(bl, sb + F_BLO + bo);
            mma16816(acc[2 * p],     ahi, bh);
            mma16816(acc[2 * p + 1], ahi, bh + 2);
            mma16816(acc[2 * p],     alo, bh);
            mma16816(acc[2 * p + 1], alo, bh + 2);
            mma16816(acc[2 * p],     ahi, bl);
            mma16816(acc[2 * p + 1], ahi, bl + 2);
        }
    }
}

// ---------------- K4: FC GEMM  grid(500), K=1024, MT=64 -----------------------
__global__ __launch_bounds__(256, 4)
void k_fc_mm(const float* __restrict__ Wfc, const float* __restrict__ bfc,
             float* __restrict__ pred) {
    extern __shared__ char dsm[];
    uint32_t base = (uint32_t)__cvta_generic_to_shared(dsm);
    const int tid = threadIdx.x, w = tid >> 5, l = tid & 31;
    const int mbase = blockIdx.x * FMT;
    const int NCH = HH / KC;         // 32

    const int arow = tid >> 2, aqq = (tid & 3) * 8;
    const int bn = tid >> 2, bq = (tid & 3) * 16;

    float acc[4][4];
#pragma unroll
    for (int i = 0; i < 4; i++)
#pragma unroll
        for (int j = 0; j < 4; j++) acc[i][j] = 0.f;

    float4 pa[2];
    auto ldgA = [&](int kg) {
        const float* src = Wfc + (size_t)(mbase + arow) * HH + kg;
        pa[0] = *(const float4*)(src + aqq);
        pa[1] = *(const float4*)(src + aqq + 4);
    };
    auto cpaB = [&](int kg, uint32_t sb) {
        cpa16(sb + F_BHI + bn * 80 + bq, (const char*)g_h1hi + (size_t)bn * HH * 2 + kg * 2 + bq);
        cpa16(sb + F_BLO + bn * 80 + bq, (const char*)g_h1lo + (size_t)bn * HH * 2 + kg * 2 + bq);
        cpa_commit();
    };

    ldgA(0);
    cpaB(0, base);
    for (int c = 0; c < NCH; c++) {
        uint32_t sb = base + (c & 1) * F_STAGE;
        stsA64(sb, pa, arow, aqq);
        if (c + 1 < NCH) {
            int kg = (c + 1) * KC;
            ldgA(kg);
            cpaB(kg, base + ((c + 1) & 1) * F_STAGE);
            cpa_wait1();
        } else {
            cpa_wait0();
        }
        __syncthreads();
        domma64(sb, acc, w, l);
        __syncthreads();
    }
    __syncthreads();

    float* ts = (float*)dsm;
    const int wq = w & 3, wh = w >> 2;
    const int gid = l >> 2, tig = (l & 3) * 2;
    float bias0 = bfc[mbase + wq * 16 + gid];
    float bias1 = bfc[mbase + wq * 16 + gid + 8];
#pragma unroll
    for (int j = 0; j < 4; j++) {
        int n = wh * 32 + j * 8 + tig;
        ts[n * 68 + wq * 16 + gid]           = acc[j][0] + bias0;
        ts[(n + 1) * 68 + wq * 16 + gid]     = acc[j][1] + bias0;
        ts[n * 68 + wq * 16 + gid + 8]       = acc[j][2] + bias1;
        ts[(n + 1) * 68 + wq * 16 + gid + 8] = acc[j][3] + bias1;
    }
    __syncthreads();
    {
        int b = tid >> 2, q = tid & 3;
        const float* srow = ts + b * 68 + q * 16;
        float* drow = pred + (size_t)b * VV + mbase + q * 16;
#pragma unroll
        for (int i = 0; i < 4; i++)
            *(float4*)(drow + i * 4) = make_float4(srow[i * 4], srow[i * 4 + 1],
                                                   srow[i * 4 + 2], srow[i * 4 + 3]);
    }
}

// ---------------- launch --------------------------------------------------------
extern "C" void kernel_launch(void* const* d_in, const int* in_sizes, int n_in,
                              void* d_out, int out_size) {
    const int*   x       = (const int*)  d_in[0];
    const float* enc     = (const float*)d_in[1];
    const float* hidden  = (const float*)d_in[2];
    const float* cell    = (const float*)d_in[3];
    const float* emb     = (const float*)d_in[4];
    const float* Wen     = (const float*)d_in[5];
    const float* be      = (const float*)d_in[6];
    const float* Wih     = (const float*)d_in[7];
    const float* Whh     = (const float*)d_in[8];
    const float* b_ih    = (const float*)d_in[9];
    const float* b_hh    = (const float*)d_in[10];
    const float* Wfc     = (const float*)d_in[11];
    const float* bfc     = (const float*)d_in[12];

    float* pred = (float*)d_out;
    float* h1o  = pred + (size_t)BB * VV;
    float* c1o  = h1o + (size_t)BB * HH;

    const int smem_attn = (CROWS * TWOH + TWOH) * sizeof(float);   // 72 KB
    cudaFuncSetAttribute(k_attn, cudaFuncAttributeMaxDynamicSharedMemorySize, smem_attn);
    cudaFuncSetAttribute(k_gates_mm, cudaFuncAttributeMaxDynamicSharedMemorySize, 2 * G_STAGE);
    cudaFuncSetAttribute(k_fc_mm, cudaFuncAttributeMaxDynamicSharedMemorySize, 2 * F_STAGE);

    k_hw<<<BB, 128>>>(hidden, Wen);
    k_attn<<<dim3(NCHUNK, BB), 256, smem_attn>>>(enc, Wen, be);
    k_combine<<<dim3(BB, 8), 256>>>(emb, x, hidden);
    k_gates_mm<<<dim3(G4 / GMT, NSPLIT), 256, 2 * G_STAGE>>>(Wih, Whh);
    k_lstm<<<(BB * HH) / 256, 256>>>(b_ih, b_hh, cell, h1o, c1o);
    k_fc_mm<<<VV / FMT, 256, 2 * F_STAGE>>>(Wfc, bfc, pred);
}